// round 13
// baseline (speedup 1.0000x reference)
#include <cuda_runtime.h>
#include <cstdint>

#define NSP     2048
#define BATCH   64
#define NSTEP   1000
#define KEX     16            // steps between ghost exchanges
#define GW      32            // ghost width per side (= 2 * KEX)
#define OWNW    64            // owned elems per warp
#define COVER   128           // OWNW + 2*GW
#define EPT     4             // elems per thread (COVER/32)
#define THREADS 512           // 16 warps per CTA -> 4 warps/SMSP
#define OWN_CTA 1024          // owned per CTA (half row)

typedef unsigned long long u64;

__device__ __forceinline__ u64 pk(float lo, float hi) {
    u64 r; asm("mov.b64 %0,{%1,%2};" : "=l"(r) : "f"(lo), "f"(hi)); return r;
}
__device__ __forceinline__ void upk(u64 v, float& lo, float& hi) {
    asm("mov.b64 {%0,%1},%2;" : "=f"(lo), "=f"(hi) : "l"(v));
}
__device__ __forceinline__ u64 fma2(u64 a, u64 b, u64 c) {
    u64 d; asm("fma.rn.f32x2 %0,%1,%2,%3;" : "=l"(d) : "l"(a), "l"(b), "l"(c)); return d;
}
__device__ __forceinline__ u64 add2(u64 a, u64 b) {
    u64 d; asm("add.rn.f32x2 %0,%1,%2;" : "=l"(d) : "l"(a), "l"(b)); return d;
}
__device__ __forceinline__ u64 mul2(u64 a, u64 b) {
    u64 d; asm("mul.rn.f32x2 %0,%1,%2;" : "=l"(d) : "l"(a), "l"(b)); return d;
}

// blocking parity wait, acquire at CLUSTER scope (peer's STS must be visible)
__device__ __forceinline__ void mbar_wait_acq_cluster(uint32_t addr, uint32_t parity) {
    asm volatile(
        "{\n\t"
        ".reg .pred P1;\n\t"
        "WAIT_LOOP_%=:\n\t"
        "mbarrier.try_wait.parity.acquire.cluster.shared::cta.b64 P1, [%0], %1, 0x989680;\n\t"
        "@P1 bra.uni WAIT_DONE_%=;\n\t"
        "bra.uni WAIT_LOOP_%=;\n\t"
        "WAIT_DONE_%=:\n\t"
        "}"
        :: "r"(addr), "r"(parity) : "memory");
}

__global__ void __cluster_dims__(2, 1, 1) __launch_bounds__(THREADS, 1)
ks_kernel(const float* __restrict__ u0,
          const float* __restrict__ cp,
          const float* __restrict__ ap,
          const float* __restrict__ bp,
          float* __restrict__ out) {
    __shared__ alignas(16) float sh_ex[2][OWN_CTA];   // double-buffered staging (8 KB)
    __shared__ alignas(8)  u64   mbar[2];             // one mbarrier per buffer parity

    const int row  = blockIdx.x >> 1;
    const int half = blockIdx.x & 1;
    const int w    = threadIdx.x >> 5;
    const int lane = threadIdx.x & 31;

    const float dt = 0.01f;
    const float Af = -0.5f * dt * (*cp);
    const float Bc = -dt * (*ap);
    const float Cc = -dt * (*bp);
    const float c0f = 1.0f - 2.0f * Bc + 6.0f * Cc;
    const float c1f = Bc - 4.0f * Cc;
    const u64 C0 = pk(c0f, c0f), C1 = pk(c1f, c1f), C2 = pk(Cc, Cc);
    const u64 AV = pk(Af, Af),   M1 = pk(-1.0f, -1.0f);

    const uint32_t shbase = (uint32_t)__cvta_generic_to_shared(&sh_ex[0][0]);
    const uint32_t mbbase = (uint32_t)__cvta_generic_to_shared(&mbar[0]);
    const uint32_t peer   = (uint32_t)(half ^ 1);

    // init mbarriers (count=1: a single remote arrive flips the phase)
    if (threadIdx.x == 0) {
        asm volatile("mbarrier.init.shared.b64 [%0], 1;" :: "r"(mbbase)     : "memory");
        asm volatile("mbarrier.init.shared.b64 [%0], 1;" :: "r"(mbbase + 8) : "memory");
    }
    __syncthreads();
    // both CTAs' mbarriers initialized before any remote arrive
    asm volatile("barrier.cluster.arrive.aligned;" ::: "memory");
    asm volatile("barrier.cluster.wait.aligned;"   ::: "memory");

    // warp cover: local coord j in [0, COVER); global row pos = base + j (mod NSP)
    const int base = half * OWN_CTA + w * OWNW - GW;   // may be negative
    const int j0   = lane * EPT;

    // owned region [GW, GW+OWNW) = [32, 96) is lane-aligned: lanes 8..23
    const bool owned = (lane >= 8) && (lane < 24);

    // ---- initial load: 1 float4 group per thread, periodic wrap ----
    u64 P0, P1;
    {
        const float* urow = u0 + (size_t)row * NSP;
        int pos = (base + j0) & (NSP - 1);
        float4 v = *reinterpret_cast<const float4*>(urow + pos);
        P0 = pk(v.x, v.y);
        P1 = pk(v.z, v.w);
    }

    // ---- frame 0 = u0 (owned lanes: coalesced 16 B per lane) ----
    if (owned) {
        float* o0 = out + (size_t)row * NSP + base + j0;
        asm volatile("st.global.cs.v2.u64 [%0], {%1,%2};"
                     :: "l"(o0), "l"(P0), "l"(P1) : "memory");
    }

    const size_t FR = (size_t)BATCH * NSP;
    float* op = out + FR + (size_t)row * NSP + (base + j0);   // frame 1 cursor

    #pragma unroll 2
    for (int t = 0; t < NSTEP; t++) {
        if (t > 0 && (t & (KEX - 1)) == 0) {
            // ===== ghost exchange via mbarrier handshake =====
            const int n  = (t >> 4) - 1;                    // exchange index
            const int q  = n & 1;                           // buffer parity
            const uint32_t ph = (uint32_t)((n >> 1) & 1);   // mbar[q] phase
            const uint32_t mb = mbbase + (uint32_t)(q * 8);

            // publish my owned 64 elems into sh_ex[q] (CTA index space)
            if (owned) {
                float a, b, c, d;
                upk(P0, a, b); upk(P1, c, d);
                *reinterpret_cast<float4*>(&sh_ex[q][w * OWNW + (j0 - GW)]) =
                    make_float4(a, b, c, d);
            }
            __syncthreads();     // all local STS done (and prior-exchange reads done)

            // signal peer: my sh_ex[q] is ready (release at cluster scope)
            if (threadIdx.x == 0) {
                asm volatile(
                    "{\n\t"
                    ".reg .b32 ra;\n\t"
                    "mapa.shared::cluster.u32 ra, %0, %1;\n\t"
                    "mbarrier.arrive.release.cluster.shared::cluster.b64 _, [ra];\n\t"
                    "}"
                    :: "r"(mb), "r"(peer) : "memory");
            }

            // wait: peer's sh_ex[q] ready (acquire at cluster scope)
            mbar_wait_acq_cluster(mb, ph);

            // refill ghost lanes from own sh_ex[q] or peer sh_ex[q] (DSMEM)
            if (!owned) {
                int pos = (base + j0) & (NSP - 1);
                int h2  = pos >> 10;            // owning half
                int idx = pos & (OWN_CTA - 1);
                float4 v;
                if (h2 == half) {
                    v = *reinterpret_cast<const float4*>(&sh_ex[q][idx]);
                } else {
                    uint32_t pa;
                    asm("mapa.shared::cluster.u32 %0, %1, %2;"
                        : "=r"(pa)
                        : "r"(shbase + (uint32_t)((q * OWN_CTA + idx) * 4)),
                          "r"(peer));
                    asm volatile("ld.shared::cluster.v4.f32 {%0,%1,%2,%3}, [%4];"
                                 : "=f"(v.x), "=f"(v.y), "=f"(v.z), "=f"(v.w)
                                 : "r"(pa));
                }
                P0 = pk(v.x, v.y);
                P1 = pk(v.z, v.w);
            }
        }

        // ===== one explicit-Euler step: 2 u64 shuffles + 14 packed ops =====
        u64 prev = __shfl_up_sync(0xffffffffu, P1, 1);    // lane-1 edge pair
        u64 next = __shfl_down_sync(0xffffffffu, P0, 1);  // lane+1 edge pair

        float a0, a1, a2, a3, a4, a5, a6, a7;
        upk(prev, a0, a1); upk(P0, a2, a3); upk(P1, a4, a5); upk(next, a6, a7);
        u64 O0 = pk(a1, a2);
        u64 O1 = pk(a3, a4);
        u64 O2 = pk(a5, a6);

        u64 r0, r1;
        {   // pair (e0,e1): um2..up2 = prev, O0, P0, O1, P1
            u64 d1 = fma2(M1, O0, O1);
            u64 t1 = fma2(AV, d1, C0);
            u64 s1 = add2(O1, O0);
            u64 s2 = add2(P1, prev);
            u64 m  = mul2(C2, s2);
            m      = fma2(C1, s1, m);
            r0     = fma2(P0, t1, m);
        }
        {   // pair (e2,e3): um2..up2 = P0, O1, P1, O2, next
            u64 d1 = fma2(M1, O1, O2);
            u64 t1 = fma2(AV, d1, C0);
            u64 s1 = add2(O2, O1);
            u64 s2 = add2(next, P0);
            u64 m  = mul2(C2, s2);
            m      = fma2(C1, s1, m);
            r1     = fma2(P1, t1, m);
        }

        // trajectory frame t+1: owned lanes, coalesced 16 B/lane, streaming
        if (owned) {
            asm volatile("st.global.cs.v2.u64 [%0], {%1,%2};"
                         :: "l"(op), "l"(r0), "l"(r1) : "memory");
        }
        op += FR;

        P0 = r0; P1 = r1;
    }

    // don't exit while peer may still access our SMEM / mbarriers
    asm volatile("barrier.cluster.arrive.aligned;" ::: "memory");
    asm volatile("barrier.cluster.wait.aligned;"   ::: "memory");
}

extern "C" void kernel_launch(void* const* d_in, const int* in_sizes, int n_in,
                              void* d_out, int out_size) {
    const float* u0    = (const float*)d_in[0];
    const float* c     = (const float*)d_in[1];
    const float* alpha = (const float*)d_in[2];
    const float* beta  = (const float*)d_in[3];
    float* out = (float*)d_out;

    ks_kernel<<<BATCH * 2, THREADS>>>(u0, c, alpha, beta, out);
}

// round 14
// speedup vs baseline: 1.1671x; 1.1671x over previous
#include <cuda_runtime.h>
#include <cstdint>

#define NSP     2048
#define BATCH   64
#define NSTEP   1000
#define KEX     32            // steps between ghost exchanges
#define GW      64            // ghost width per side (= 2 * KEX)
#define OWNW    128           // owned elems per warp
#define COVER   256           // OWNW + 2*GW
#define EPT     8             // elems per thread (COVER/32)
#define THREADS 256           // 8 warps per CTA -> 2 warps/SMSP
#define OWN_CTA 1024          // owned per CTA (half row)

typedef unsigned long long u64;

__device__ __forceinline__ u64 pk(float lo, float hi) {
    u64 r; asm("mov.b64 %0,{%1,%2};" : "=l"(r) : "f"(lo), "f"(hi)); return r;
}
__device__ __forceinline__ void upk(u64 v, float& lo, float& hi) {
    asm("mov.b64 {%0,%1},%2;" : "=f"(lo), "=f"(hi) : "l"(v));
}
__device__ __forceinline__ u64 fma2(u64 a, u64 b, u64 c) {
    u64 d; asm("fma.rn.f32x2 %0,%1,%2,%3;" : "=l"(d) : "l"(a), "l"(b), "l"(c)); return d;
}
__device__ __forceinline__ u64 add2(u64 a, u64 b) {
    u64 d; asm("add.rn.f32x2 %0,%1,%2;" : "=l"(d) : "l"(a), "l"(b)); return d;
}
__device__ __forceinline__ u64 mul2(u64 a, u64 b) {
    u64 d; asm("mul.rn.f32x2 %0,%1,%2;" : "=l"(d) : "l"(a), "l"(b)); return d;
}

// branch-free predicated pair of 16B streaming stores (no BSSY/BSYNC)
__device__ __forceinline__ void st2_pred(int pred, float* p,
                                         u64 a, u64 b, u64 c, u64 d) {
    asm volatile(
        "{\n\t"
        ".reg .pred q;\n\t"
        "setp.ne.s32 q, %0, 0;\n\t"
        "@q st.global.cs.v2.u64 [%1], {%2,%3};\n\t"
        "@q st.global.cs.v2.u64 [%4], {%5,%6};\n\t"
        "}"
        :: "r"(pred), "l"(p), "l"(a), "l"(b), "l"(p + 4), "l"(c), "l"(d)
        : "memory");
}

// blocking parity wait, acquire at CLUSTER scope (peer's STS must be visible)
__device__ __forceinline__ void mbar_wait_acq_cluster(uint32_t addr, uint32_t parity) {
    asm volatile(
        "{\n\t"
        ".reg .pred P1;\n\t"
        "WAIT_LOOP_%=:\n\t"
        "mbarrier.try_wait.parity.acquire.cluster.shared::cta.b64 P1, [%0], %1, 0x989680;\n\t"
        "@P1 bra.uni WAIT_DONE_%=;\n\t"
        "bra.uni WAIT_LOOP_%=;\n\t"
        "WAIT_DONE_%=:\n\t"
        "}"
        :: "r"(addr), "r"(parity) : "memory");
}

__global__ void __cluster_dims__(2, 1, 1) __launch_bounds__(THREADS, 1)
ks_kernel(const float* __restrict__ u0,
          const float* __restrict__ cp,
          const float* __restrict__ ap,
          const float* __restrict__ bp,
          float* __restrict__ out) {
    __shared__ alignas(16) float sh_ex[2][OWN_CTA];   // double-buffered staging (8 KB)
    __shared__ alignas(8)  u64   mbar[2];             // one mbarrier per buffer parity

    const int row  = blockIdx.x >> 1;
    const int half = blockIdx.x & 1;
    const int w    = threadIdx.x >> 5;
    const int lane = threadIdx.x & 31;

    const float dt = 0.01f;
    const float Af = -0.5f * dt * (*cp);
    const float Bc = -dt * (*ap);
    const float Cc = -dt * (*bp);
    const float c0f = 1.0f - 2.0f * Bc + 6.0f * Cc;
    const float c1f = Bc - 4.0f * Cc;
    const u64 C0 = pk(c0f, c0f), C1 = pk(c1f, c1f), C2 = pk(Cc, Cc);
    const u64 AV = pk(Af, Af),   M1 = pk(-1.0f, -1.0f);

    const uint32_t shbase = (uint32_t)__cvta_generic_to_shared(&sh_ex[0][0]);
    const uint32_t mbbase = (uint32_t)__cvta_generic_to_shared(&mbar[0]);
    const uint32_t peer   = (uint32_t)(half ^ 1);

    // init mbarriers (count=1: a single remote arrive flips the phase)
    if (threadIdx.x == 0) {
        asm volatile("mbarrier.init.shared.b64 [%0], 1;" :: "r"(mbbase)     : "memory");
        asm volatile("mbarrier.init.shared.b64 [%0], 1;" :: "r"(mbbase + 8) : "memory");
    }
    __syncthreads();
    // both CTAs' mbarriers initialized before any remote arrive
    asm volatile("barrier.cluster.arrive.aligned;" ::: "memory");
    asm volatile("barrier.cluster.wait.aligned;"   ::: "memory");

    // warp cover: local coord j in [0, COVER); global row pos = base + j (mod NSP)
    const int base = half * OWN_CTA + w * OWNW - GW;   // may be negative
    const int j0   = lane * EPT;

    // owned region [GW, GW+OWNW) = [64, 192) is lane-aligned: lanes 8..23
    const bool owned = (lane >= 8) && (lane < 24);
    const int  ownp  = owned ? 1 : 0;                  // predicate as int

    // ---- initial load: 2 float4 groups per thread, periodic wrap ----
    u64 P[4];
    const float* urow = u0 + (size_t)row * NSP;
    #pragma unroll
    for (int g = 0; g < 2; g++) {
        int pos = (base + j0 + 4 * g) & (NSP - 1);
        float4 v = *reinterpret_cast<const float4*>(urow + pos);
        P[2 * g]     = pk(v.x, v.y);
        P[2 * g + 1] = pk(v.z, v.w);
    }

    // ---- frame 0 = u0 (owned lanes: fully coalesced, branch-free) ----
    st2_pred(ownp, out + (size_t)row * NSP + base + j0, P[0], P[1], P[2], P[3]);

    const size_t FR = (size_t)BATCH * NSP;
    float* op = out + FR + (size_t)row * NSP + (base + j0);   // frame 1 cursor

    #pragma unroll 2
    for (int t = 0; t < NSTEP; t++) {
        if (t > 0 && (t & (KEX - 1)) == 0) {
            // ===== ghost exchange via mbarrier handshake =====
            const int n  = (t >> 5) - 1;            // exchange index 0..30
            const int q  = n & 1;                   // buffer parity
            const uint32_t ph = (uint32_t)((n >> 1) & 1);   // mbar[q] phase
            const uint32_t mb = mbbase + (uint32_t)(q * 8);

            // publish my owned 128 elems into sh_ex[q] (CTA index space)
            if (owned) {
                float a, b, c, d;
                float* s = &sh_ex[q][w * OWNW + (j0 - GW)];
                upk(P[0], a, b); upk(P[1], c, d);
                reinterpret_cast<float4*>(s)[0] = make_float4(a, b, c, d);
                upk(P[2], a, b); upk(P[3], c, d);
                reinterpret_cast<float4*>(s)[1] = make_float4(a, b, c, d);
            }
            __syncthreads();     // all local STS done (and prior-exchange reads done)

            // signal peer: my sh_ex[q] is ready (release at cluster scope)
            if (threadIdx.x == 0) {
                asm volatile(
                    "{\n\t"
                    ".reg .b32 ra;\n\t"
                    "mapa.shared::cluster.u32 ra, %0, %1;\n\t"
                    "mbarrier.arrive.release.cluster.shared::cluster.b64 _, [ra];\n\t"
                    "}"
                    :: "r"(mb), "r"(peer) : "memory");
            }

            // wait: peer's sh_ex[q] ready (acquire at cluster scope)
            mbar_wait_acq_cluster(mb, ph);

            // refill ghost lanes from own sh_ex[q] or peer sh_ex[q] (DSMEM)
            if (!owned) {
                #pragma unroll
                for (int g = 0; g < 2; g++) {
                    int pos = (base + j0 + 4 * g) & (NSP - 1);
                    int h2  = pos >> 10;            // owning half
                    int idx = pos & (OWN_CTA - 1);
                    float4 v;
                    if (h2 == half) {
                        v = *reinterpret_cast<const float4*>(&sh_ex[q][idx]);
                    } else {
                        uint32_t pa;
                        asm("mapa.shared::cluster.u32 %0, %1, %2;"
                            : "=r"(pa)
                            : "r"(shbase + (uint32_t)((q * OWN_CTA + idx) * 4)),
                              "r"(peer));
                        asm volatile("ld.shared::cluster.v4.f32 {%0,%1,%2,%3}, [%4];"
                                     : "=f"(v.x), "=f"(v.y), "=f"(v.z), "=f"(v.w)
                                     : "r"(pa));
                    }
                    P[2 * g]     = pk(v.x, v.y);
                    P[2 * g + 1] = pk(v.z, v.w);
                }
            }
        }

        // ===== one explicit-Euler step, registers + 2 u64 shuffles =====
        u64 prev = __shfl_up_sync(0xffffffffu, P[3], 1);   // lane-1's edge pair
        u64 next = __shfl_down_sync(0xffffffffu, P[0], 1); // lane+1's edge pair

        u64 A[6];
        A[0] = prev; A[1] = P[0]; A[2] = P[1]; A[3] = P[2]; A[4] = P[3]; A[5] = next;

        float a[12];
        #pragma unroll
        for (int i = 0; i < 6; i++) upk(A[i], a[2 * i], a[2 * i + 1]);
        u64 O[5];
        #pragma unroll
        for (int i = 0; i < 5; i++) O[i] = pk(a[2 * i + 1], a[2 * i + 2]);

        u64 r[4];
        #pragma unroll
        for (int p = 0; p < 4; p++) {
            u64 u   = A[p + 1];
            u64 d1  = fma2(M1, O[p], O[p + 1]);     // up1 - um1
            u64 t1  = fma2(AV, d1, C0);             // c0 + A*d1
            u64 s1  = add2(O[p + 1], O[p]);
            u64 s2  = add2(A[p + 2], A[p]);
            u64 m   = mul2(C2, s2);
            m       = fma2(C1, s1, m);
            r[p]    = fma2(u, t1, m);               // u*(c0+A*d1) + C1*s1 + C2*s2
        }

        // trajectory frame t+1: branch-free predicated coalesced stores
        st2_pred(ownp, op, r[0], r[1], r[2], r[3]);
        op += FR;

        P[0] = r[0]; P[1] = r[1]; P[2] = r[2]; P[3] = r[3];
    }

    // don't exit while peer may still access our SMEM / mbarriers
    asm volatile("barrier.cluster.arrive.aligned;" ::: "memory");
    asm volatile("barrier.cluster.wait.aligned;"   ::: "memory");
}

extern "C" void kernel_launch(void* const* d_in, const int* in_sizes, int n_in,
                              void* d_out, int out_size) {
    const float* u0    = (const float*)d_in[0];
    const float* c     = (const float*)d_in[1];
    const float* alpha = (const float*)d_in[2];
    const float* beta  = (const float*)d_in[3];
    float* out = (float*)d_out;

    ks_kernel<<<BATCH * 2, THREADS>>>(u0, c, alpha, beta, out);
}